// round 12
// baseline (speedup 1.0000x reference)
#include <cuda_runtime.h>

#define T_TRIG 48
#define S_SPAN 128
#define NNODE  (T_TRIG * S_SPAN)     // 6144
#define DIM    128
#define NHEADS 4
#define HDIM   32

typedef unsigned long long ull;
typedef unsigned int uint;

__device__ float g_h   [NNODE * DIM];
__device__ float g_A   [NNODE * NHEADS];
__device__ float g_B   [NNODE * NHEADS];
__device__ float g_EA  [NNODE * NHEADS];
__device__ float g_EA5 [NNODE * NHEADS];
__device__ float g_EB  [NNODE * NHEADS];
__device__ float g_EB5 [NNODE * NHEADS];
__device__ float g_srow[NNODE * NHEADS];
__device__ float g_tmp [NNODE * DIM];
__device__ float g_x1  [NNODE * DIM];
__device__ float4 g_Wf [2 * 16 * 16 * 32];

// ---- tf32 helpers -----------------------------------------------------------
__device__ __forceinline__ uint cvt_tf32(float f) {
    uint r; asm("cvt.rna.tf32.f32 %0, %1;" : "=r"(r) : "f"(f)); return r;
}
__device__ __forceinline__ void mma_tf32(float& d0, float& d1, float& d2, float& d3,
                                         uint a0, uint a1, uint a2, uint a3,
                                         uint b0, uint b1) {
    asm("mma.sync.aligned.m16n8k8.row.col.f32.tf32.tf32.f32 "
        "{%0,%1,%2,%3}, {%4,%5,%6,%7}, {%8,%9}, {%0,%1,%2,%3};"
        : "+f"(d0), "+f"(d1), "+f"(d2), "+f"(d3)
        : "r"(a0), "r"(a1), "r"(a2), "r"(a3), "r"(b0), "r"(b1));
}

// ---------------------------------------------------------------------------
// K0: pack W1/W2 into fragment order with tf32 hi/lo split. (unchanged R10)
// ---------------------------------------------------------------------------
__global__ void __launch_bounds__(256)
k_prep(const float* __restrict__ W1, const float* __restrict__ W2)
{
    const int gid   = blockIdx.x * 256 + threadIdx.x;
    const int layer = gid >> 13;
    const int e     = gid & 8191;
    const int lane  = e & 31;
    const int nt    = (e >> 5) & 15;
    const int ks    = e >> 9;

    const float* W = layer ? W2 : W1;
    const int k0 = ks * 8 + (lane & 3);
    const int n  = nt * 8 + (lane >> 2);

    const float b0 = W[k0 * 128 + n];
    const float b1 = W[(k0 + 4) * 128 + n];
    const uint b0h = cvt_tf32(b0);
    const uint b1h = cvt_tf32(b1);
    const uint b0l = cvt_tf32(b0 - __uint_as_float(b0h));
    const uint b1l = cvt_tf32(b1 - __uint_as_float(b1h));

    g_Wf[layer * 8192 + e] = make_float4(__uint_as_float(b0h), __uint_as_float(b1h),
                                         __uint_as_float(b0l), __uint_as_float(b1l));
}

// ---------------------------------------------------------------------------
// K1: h = x @ W via tensor cores (3xTF32) + attention dots + 4 exps.
// (unchanged from R10 win)
// ---------------------------------------------------------------------------
__global__ void __launch_bounds__(128)
k_gemm_attn(const float* __restrict__ x,
            const float4* __restrict__ Wf,
            const float* __restrict__ att_src,
            const float* __restrict__ att_dst)
{
    __shared__ __align__(16) float xs[16 * 132];

    const int tid  = threadIdx.x;
    const int row0 = blockIdx.x * 16;

#pragma unroll
    for (int i = 0; i < 4; i++) {
        const int idx = tid + 128 * i;
        const int row = idx >> 5, c4 = idx & 31;
        *(float4*)&xs[row * 132 + c4 * 4] =
            ((const float4*)(x + row0 * 128))[idx];
    }
    __syncthreads();

    const int warp = tid >> 5;
    const int lane = tid & 31;
    const int gid  = lane >> 2;
    const int tig  = lane & 3;

    float d[4][4];
#pragma unroll
    for (int nt = 0; nt < 4; nt++)
#pragma unroll
        for (int i = 0; i < 4; i++) d[nt][i] = 0.f;

#pragma unroll 4
    for (int ks = 0; ks < 16; ks++) {
        const float a0f = xs[gid * 132 + ks * 8 + tig];
        const float a1f = xs[(gid + 8) * 132 + ks * 8 + tig];
        const float a2f = xs[gid * 132 + ks * 8 + tig + 4];
        const float a3f = xs[(gid + 8) * 132 + ks * 8 + tig + 4];
        const uint ah0 = cvt_tf32(a0f), ah1 = cvt_tf32(a1f);
        const uint ah2 = cvt_tf32(a2f), ah3 = cvt_tf32(a3f);
        const uint al0 = cvt_tf32(a0f - __uint_as_float(ah0));
        const uint al1 = cvt_tf32(a1f - __uint_as_float(ah1));
        const uint al2 = cvt_tf32(a2f - __uint_as_float(ah2));
        const uint al3 = cvt_tf32(a3f - __uint_as_float(ah3));

#pragma unroll
        for (int nt = 0; nt < 4; nt++) {
            const float4 bf = __ldg(&Wf[(ks * 16 + warp * 4 + nt) * 32 + lane]);
            const uint bh0 = __float_as_uint(bf.x);
            const uint bh1 = __float_as_uint(bf.y);
            const uint bl0 = __float_as_uint(bf.z);
            const uint bl1 = __float_as_uint(bf.w);
            mma_tf32(d[nt][0], d[nt][1], d[nt][2], d[nt][3],
                     ah0, ah1, ah2, ah3, bh0, bh1);
            mma_tf32(d[nt][0], d[nt][1], d[nt][2], d[nt][3],
                     ah0, ah1, ah2, ah3, bl0, bl1);
            mma_tf32(d[nt][0], d[nt][1], d[nt][2], d[nt][3],
                     al0, al1, al2, al3, bh0, bh1);
        }
    }

    float psr0 = 0.f, psr8 = 0.f, pdr0 = 0.f, pdr8 = 0.f;
#pragma unroll
    for (int nt = 0; nt < 4; nt++) {
        const int col = warp * 32 + nt * 8 + 2 * tig;
        *(float2*)&g_h[(row0 + gid) * 128 + col]     = make_float2(d[nt][0], d[nt][1]);
        *(float2*)&g_h[(row0 + gid + 8) * 128 + col] = make_float2(d[nt][2], d[nt][3]);

        const float2 as = *(const float2*)&att_src[col];
        const float2 ad = *(const float2*)&att_dst[col];
        psr0 += d[nt][0] * as.x + d[nt][1] * as.y;
        psr8 += d[nt][2] * as.x + d[nt][3] * as.y;
        pdr0 += d[nt][0] * ad.x + d[nt][1] * ad.y;
        pdr8 += d[nt][2] * ad.x + d[nt][3] * ad.y;
    }
#pragma unroll
    for (int o = 1; o < 4; o <<= 1) {
        psr0 += __shfl_xor_sync(0xffffffffu, psr0, o);
        psr8 += __shfl_xor_sync(0xffffffffu, psr8, o);
        pdr0 += __shfl_xor_sync(0xffffffffu, pdr0, o);
        pdr8 += __shfl_xor_sync(0xffffffffu, pdr8, o);
    }
    if (tig == 0) {
        const int n0 = row0 + gid;
        const int n8 = row0 + gid + 8;
        int i4 = n0 * 4 + warp;
        g_A[i4] = psr0;  g_B[i4] = pdr0;
        g_EA[i4]  = __expf(psr0);        g_EB[i4]  = __expf(pdr0);
        g_EA5[i4] = __expf(0.2f * psr0); g_EB5[i4] = __expf(0.2f * pdr0);
        i4 = n8 * 4 + warp;
        g_A[i4] = psr8;  g_B[i4] = pdr8;
        g_EA[i4]  = __expf(psr8);        g_EB[i4]  = __expf(pdr8);
        g_EA5[i4] = __expf(0.2f * psr8); g_EB5[i4] = __expf(0.2f * pdr8);
    }
}

// ---------------------------------------------------------------------------
// K2: row aggregation via sorted prefix sums. Block = (r, head), grid = 192,
// 128 threads. out_c = EB_c*(T_hi - P_hi[R_c]) + EB5_c*P_lo[R_c],
// R_c = #{j : A_j <= -B_c} over sorted A. Also writes row denominator part.
// ---------------------------------------------------------------------------
__global__ void __launch_bounds__(128)
k_row_agg()
{
    const int r   = blockIdx.x >> 2;
    const int hh  = blockIdx.x & 3;
    const int tid = threadIdx.x;

    __shared__ float keys[128];
    __shared__ int   sidx[128];
    __shared__ float EAu[128], EA5u[128];
    __shared__ float Bu[128], EBu[128], EB5u[128];
    __shared__ float Vhi[128][33];
    __shared__ float Vlo[128][33];
    __shared__ float Pe[128], Pe5[128];

    {
        const int idx = (r * 128 + tid) * 4 + hh;
        keys[tid] = g_A[idx];
        sidx[tid] = tid;
        EAu [tid] = g_EA [idx];
        EA5u[tid] = g_EA5[idx];
        Bu  [tid] = g_B  [idx];
        EBu [tid] = g_EB [idx];
        EB5u[tid] = g_EB5[idx];
    }
    __syncthreads();

    // bitonic sort ascending, 128 keys, 64 compare-exchanges per pass
    for (int k = 2; k <= 128; k <<= 1) {
        for (int j = k >> 1; j > 0; j >>= 1) {
            if (tid < 64) {
                const int i = ((tid & ~(j - 1)) << 1) | (tid & (j - 1));
                const int p = i | j;
                const bool up = ((i & k) == 0);
                const float a = keys[i], b = keys[p];
                if ((a > b) == up) {
                    keys[i] = b; keys[p] = a;
                    const int t2 = sidx[i]; sidx[i] = sidx[p]; sidx[p] = t2;
                }
            }
            __syncthreads();
        }
    }

    // build V tables: Vhi[k][d] = EA_sorted[k]*h_sorted[k][d], Vlo with EA5
    {
        const int j = sidx[tid];
        const float ea  = EAu[j];
        const float ea5 = EA5u[j];
        const float* hp = &g_h[(r * 128 + j) * 128 + hh * 32];
#pragma unroll
        for (int v = 0; v < 8; v++) {
            const float4 hv = *(const float4*)&hp[v * 4];
            Vhi[tid][v*4+0] = ea  * hv.x;  Vlo[tid][v*4+0] = ea5 * hv.x;
            Vhi[tid][v*4+1] = ea  * hv.y;  Vlo[tid][v*4+1] = ea5 * hv.y;
            Vhi[tid][v*4+2] = ea  * hv.z;  Vlo[tid][v*4+2] = ea5 * hv.z;
            Vhi[tid][v*4+3] = ea  * hv.w;  Vlo[tid][v*4+3] = ea5 * hv.w;
        }
    }
    __syncthreads();

    // inclusive scans along sorted order (in place)
    if (tid < 32) {
        float acc = 0.f;
        for (int k = 0; k < 128; k++) { acc += Vhi[k][tid]; Vhi[k][tid] = acc; }
    } else if (tid < 64) {
        const int d = tid - 32;
        float acc = 0.f;
        for (int k = 0; k < 128; k++) { acc += Vlo[k][d]; Vlo[k][d] = acc; }
    } else if (tid == 64) {
        float acc = 0.f;
        for (int k = 0; k < 128; k++) { acc += EAu[sidx[k]]; Pe[k] = acc; }
    } else if (tid == 65) {
        float acc = 0.f;
        for (int k = 0; k < 128; k++) { acc += EA5u[sidx[k]]; Pe5[k] = acc; }
    }
    __syncthreads();

    // per-dst combine: c = tid
    {
        const int c = tid;
        const float x = -Bu[c];
        int lo = 0, hi2 = 128;
        while (lo < hi2) {
            const int mid = (lo + hi2) >> 1;
            if (keys[mid] <= x) lo = mid + 1; else hi2 = mid;
        }
        const int R  = lo;
        const float f  = (R > 0) ? 1.f : 0.f;
        const int  Rm  = (R > 0) ? (R - 1) : 0;
        const float eb = EBu[c], eb5 = EB5u[c];

        g_srow[(r * 128 + c) * 4 + hh] =
            eb * (Pe[127] - f * Pe[Rm]) + eb5 * (f * Pe5[Rm]);

        float* op = &g_tmp[(r * 128 + c) * 128 + hh * 32];
#pragma unroll
        for (int v = 0; v < 8; v++) {
            float4 o;
            o.x = eb * (Vhi[127][v*4+0] - f * Vhi[Rm][v*4+0]) + eb5 * (f * Vlo[Rm][v*4+0]);
            o.y = eb * (Vhi[127][v*4+1] - f * Vhi[Rm][v*4+1]) + eb5 * (f * Vlo[Rm][v*4+1]);
            o.z = eb * (Vhi[127][v*4+2] - f * Vhi[Rm][v*4+2]) + eb5 * (f * Vlo[Rm][v*4+2]);
            o.w = eb * (Vhi[127][v*4+3] - f * Vhi[Rm][v*4+3]) + eb5 * (f * Vlo[Rm][v*4+3]);
            *(float4*)&op[v * 4] = o;
        }
    }
}

// ---------------------------------------------------------------------------
// K3: column aggregation via sorted prefix sums (48 srcs, self excluded by
// exact subtraction) + denominator finalize + normalize + bias + ELU.
// Block = (c, head), grid = 512, 128 threads.
// ---------------------------------------------------------------------------
__global__ void __launch_bounds__(128)
k_col_agg(const float* __restrict__ bias, float* __restrict__ out)
{
    const int c   = blockIdx.x >> 2;
    const int hh  = blockIdx.x & 3;
    const int tid = threadIdx.x;

    __shared__ float keys[64];
    __shared__ int   sidx[64];
    __shared__ float Au[48], EAu[48], EA5u[48];
    __shared__ float Bu[48], EBu[48], EB5u[48], Srw[48];
    __shared__ float Vhi[64][33];
    __shared__ float Vlo[64][33];
    __shared__ float Pe[64], Pe5[64];
    __shared__ float bsh[32];

    if (tid < 48) {
        const int idx = (tid * 128 + c) * 4 + hh;
        const float a = g_A[idx];
        Au[tid]   = a;
        keys[tid] = a;
        sidx[tid] = tid;
        EAu [tid] = g_EA  [idx];
        EA5u[tid] = g_EA5 [idx];
        Bu  [tid] = g_B   [idx];
        EBu [tid] = g_EB  [idx];
        EB5u[tid] = g_EB5 [idx];
        Srw [tid] = g_srow[idx];
    } else if (tid < 64) {
        keys[tid] = 1e30f;     // pad: larger than any threshold
        sidx[tid] = -1;
    } else if (tid < 96) {
        bsh[tid - 64] = bias[hh * 32 + (tid - 64)];
    }
    __syncthreads();

    // bitonic sort ascending, 64 keys, 32 CE per pass
    for (int k = 2; k <= 64; k <<= 1) {
        for (int j = k >> 1; j > 0; j >>= 1) {
            if (tid < 32) {
                const int i = ((tid & ~(j - 1)) << 1) | (tid & (j - 1));
                const int p = i | j;
                const bool up = ((i & k) == 0);
                const float a = keys[i], b = keys[p];
                if ((a > b) == up) {
                    keys[i] = b; keys[p] = a;
                    const int t2 = sidx[i]; sidx[i] = sidx[p]; sidx[p] = t2;
                }
            }
            __syncthreads();
        }
    }

    // build V tables (padded slots -> zero)
    if (tid < 64) {
        const int j = sidx[tid];
        if (j >= 0) {
            const float ea  = EAu[j];
            const float ea5 = EA5u[j];
            const float* hp = &g_h[(j * 128 + c) * 128 + hh * 32];
#pragma unroll
            for (int v = 0; v < 8; v++) {
                const float4 hv = *(const float4*)&hp[v * 4];
                Vhi[tid][v*4+0] = ea  * hv.x;  Vlo[tid][v*4+0] = ea5 * hv.x;
                Vhi[tid][v*4+1] = ea  * hv.y;  Vlo[tid][v*4+1] = ea5 * hv.y;
                Vhi[tid][v*4+2] = ea  * hv.z;  Vlo[tid][v*4+2] = ea5 * hv.z;
                Vhi[tid][v*4+3] = ea  * hv.w;  Vlo[tid][v*4+3] = ea5 * hv.w;
            }
        } else {
#pragma unroll
            for (int d = 0; d < 32; d++) { Vhi[tid][d] = 0.f; Vlo[tid][d] = 0.f; }
        }
    }
    __syncthreads();

    if (tid < 32) {
        float acc = 0.f;
        for (int k = 0; k < 64; k++) { acc += Vhi[k][tid]; Vhi[k][tid] = acc; }
    } else if (tid < 64) {
        const int d = tid - 32;
        float acc = 0.f;
        for (int k = 0; k < 64; k++) { acc += Vlo[k][d]; Vlo[k][d] = acc; }
    } else if (tid == 64) {
        float acc = 0.f;
        for (int k = 0; k < 64; k++) {
            const int j = sidx[k];
            acc += (j >= 0) ? EAu[j] : 0.f;
            Pe[k] = acc;
        }
    } else if (tid == 65) {
        float acc = 0.f;
        for (int k = 0; k < 64; k++) {
            const int j = sidx[k];
            acc += (j >= 0) ? EA5u[j] : 0.f;
            Pe5[k] = acc;
        }
    }
    __syncthreads();

    // combine: dst r = tid (0..47)
    if (tid < 48) {
        const int rr = tid;
        const float Bv = Bu[rr];
        const float x  = -Bv;
        int lo = 0, hi2 = 64;
        while (lo < hi2) {
            const int mid = (lo + hi2) >> 1;
            if (keys[mid] <= x) lo = mid + 1; else hi2 = mid;
        }
        const int R  = lo;
        const float f = (R > 0) ? 1.f : 0.f;
        const int  Rm = (R > 0) ? (R - 1) : 0;
        const float eb = EBu[rr], eb5 = EB5u[rr];

        // exact self-term (same predicate as aggregate -> exact subtraction)
        const float xs = Au[rr] + Bv;
        const float wself = xs > 0.f ? EAu[rr] * eb : EA5u[rr] * eb5;

        const float scol = eb * (Pe[63] - f * Pe[Rm]) + eb5 * (f * Pe5[Rm]) - wself;
        const float rd = 1.f / (Srw[rr] + scol);

        const float* hs = &g_h  [(rr * 128 + c) * 128 + hh * 32];
        const float* tp = &g_tmp[(rr * 128 + c) * 128 + hh * 32];
        float*       op = &out  [(rr * 128 + c) * 128 + hh * 32];

#pragma unroll
        for (int v = 0; v < 8; v++) {
            const float4 hv = *(const float4*)&hs[v * 4];
            const float4 tv = *(const float4*)&tp[v * 4];
            float vals[4];
            vals[0] = eb * (Vhi[63][v*4+0] - f * Vhi[Rm][v*4+0]) + eb5 * (f * Vlo[Rm][v*4+0]) - wself * hv.x;
            vals[1] = eb * (Vhi[63][v*4+1] - f * Vhi[Rm][v*4+1]) + eb5 * (f * Vlo[Rm][v*4+1]) - wself * hv.y;
            vals[2] = eb * (Vhi[63][v*4+2] - f * Vhi[Rm][v*4+2]) + eb5 * (f * Vlo[Rm][v*4+2]) - wself * hv.z;
            vals[3] = eb * (Vhi[63][v*4+3] - f * Vhi[Rm][v*4+3]) + eb5 * (f * Vlo[Rm][v*4+3]) - wself * hv.w;
            const float tvv[4] = {tv.x, tv.y, tv.z, tv.w};
            float4 o;
            float* oc = (float*)&o;
#pragma unroll
            for (int e = 0; e < 4; e++) {
                float vv = (tvv[e] + vals[e]) * rd + bsh[v * 4 + e];
                oc[e] = vv > 0.f ? vv : (__expf(vv) - 1.f);
            }
            *(float4*)&op[v * 4] = o;
        }
    }
}

// ---------------------------------------------------------------------------
static void run_layer(const float* x, const float4* Wf, const float* asrc,
                      const float* adst, const float* bias, float* out)
{
    k_gemm_attn<<<NNODE / 16, 128>>>(x, Wf, asrc, adst);
    k_row_agg<<<T_TRIG * NHEADS, 128>>>();
    k_col_agg<<<S_SPAN * NHEADS, 128>>>(bias, out);
}

extern "C" void kernel_launch(void* const* d_in, const int* in_sizes, int n_in,
                              void* d_out, int out_size)
{
    const float* x0  = (const float*)d_in[0];
    const float* W1  = (const float*)d_in[1];
    const float* as1 = (const float*)d_in[2];
    const float* ad1 = (const float*)d_in[3];
    const float* b1  = (const float*)d_in[4];
    const float* W2  = (const float*)d_in[5];
    const float* as2 = (const float*)d_in[6];
    const float* ad2 = (const float*)d_in[7];
    const float* b2  = (const float*)d_in[8];

    float* x1 = nullptr;
    cudaGetSymbolAddress((void**)&x1, g_x1);
    float4* Wf = nullptr;
    cudaGetSymbolAddress((void**)&Wf, g_Wf);

    k_prep<<<64, 256>>>(W1, W2);
    run_layer(x0, Wf,        as1, ad1, b1, x1);
    run_layer(x1, Wf + 8192, as2, ad2, b2, (float*)d_out);
}

// round 13
// speedup vs baseline: 1.3168x; 1.3168x over previous
#include <cuda_runtime.h>

#define T_TRIG 48
#define S_SPAN 128
#define NNODE  (T_TRIG * S_SPAN)     // 6144
#define DIM    128
#define NHEADS 4
#define HDIM   32

typedef unsigned long long ull;
typedef unsigned int uint;

__device__ float g_h   [NNODE * DIM];
__device__ float g_A   [NNODE * NHEADS];
__device__ float g_B   [NNODE * NHEADS];
__device__ float g_EA  [NNODE * NHEADS];
__device__ float g_EA5 [NNODE * NHEADS];
__device__ float g_EB  [NNODE * NHEADS];
__device__ float g_EB5 [NNODE * NHEADS];
__device__ float g_srow[NNODE * NHEADS];
__device__ float g_tmp [NNODE * DIM];
__device__ float g_x1  [NNODE * DIM];
__device__ float4 g_Wf [2 * 16 * 16 * 32];

// ---- tf32 helpers -----------------------------------------------------------
__device__ __forceinline__ uint cvt_tf32(float f) {
    uint r; asm("cvt.rna.tf32.f32 %0, %1;" : "=r"(r) : "f"(f)); return r;
}
__device__ __forceinline__ void mma_tf32(float& d0, float& d1, float& d2, float& d3,
                                         uint a0, uint a1, uint a2, uint a3,
                                         uint b0, uint b1) {
    asm("mma.sync.aligned.m16n8k8.row.col.f32.tf32.tf32.f32 "
        "{%0,%1,%2,%3}, {%4,%5,%6,%7}, {%8,%9}, {%0,%1,%2,%3};"
        : "+f"(d0), "+f"(d1), "+f"(d2), "+f"(d3)
        : "r"(a0), "r"(a1), "r"(a2), "r"(a3), "r"(b0), "r"(b1));
}

// ---------------------------------------------------------------------------
// K0: pack W1/W2 into fragment order with tf32 hi/lo split. (R10, unchanged)
// ---------------------------------------------------------------------------
__global__ void __launch_bounds__(256)
k_prep(const float* __restrict__ W1, const float* __restrict__ W2)
{
    const int gid   = blockIdx.x * 256 + threadIdx.x;
    const int layer = gid >> 13;
    const int e     = gid & 8191;
    const int lane  = e & 31;
    const int nt    = (e >> 5) & 15;
    const int ks    = e >> 9;

    const float* W = layer ? W2 : W1;
    const int k0 = ks * 8 + (lane & 3);
    const int n  = nt * 8 + (lane >> 2);

    const float b0 = W[k0 * 128 + n];
    const float b1 = W[(k0 + 4) * 128 + n];
    const uint b0h = cvt_tf32(b0);
    const uint b1h = cvt_tf32(b1);
    const uint b0l = cvt_tf32(b0 - __uint_as_float(b0h));
    const uint b1l = cvt_tf32(b1 - __uint_as_float(b1h));

    g_Wf[layer * 8192 + e] = make_float4(__uint_as_float(b0h), __uint_as_float(b1h),
                                         __uint_as_float(b0l), __uint_as_float(b1l));
}

// ---------------------------------------------------------------------------
// K1: h = x @ W via tensor cores (3xTF32) + attention dots + 4 exps. (R10)
// ---------------------------------------------------------------------------
__global__ void __launch_bounds__(128)
k_gemm_attn(const float* __restrict__ x,
            const float4* __restrict__ Wf,
            const float* __restrict__ att_src,
            const float* __restrict__ att_dst)
{
    __shared__ __align__(16) float xs[16 * 132];

    const int tid  = threadIdx.x;
    const int row0 = blockIdx.x * 16;

#pragma unroll
    for (int i = 0; i < 4; i++) {
        const int idx = tid + 128 * i;
        const int row = idx >> 5, c4 = idx & 31;
        *(float4*)&xs[row * 132 + c4 * 4] =
            ((const float4*)(x + row0 * 128))[idx];
    }
    __syncthreads();

    const int warp = tid >> 5;
    const int lane = tid & 31;
    const int gid  = lane >> 2;
    const int tig  = lane & 3;

    float d[4][4];
#pragma unroll
    for (int nt = 0; nt < 4; nt++)
#pragma unroll
        for (int i = 0; i < 4; i++) d[nt][i] = 0.f;

#pragma unroll 4
    for (int ks = 0; ks < 16; ks++) {
        const float a0f = xs[gid * 132 + ks * 8 + tig];
        const float a1f = xs[(gid + 8) * 132 + ks * 8 + tig];
        const float a2f = xs[gid * 132 + ks * 8 + tig + 4];
        const float a3f = xs[(gid + 8) * 132 + ks * 8 + tig + 4];
        const uint ah0 = cvt_tf32(a0f), ah1 = cvt_tf32(a1f);
        const uint ah2 = cvt_tf32(a2f), ah3 = cvt_tf32(a3f);
        const uint al0 = cvt_tf32(a0f - __uint_as_float(ah0));
        const uint al1 = cvt_tf32(a1f - __uint_as_float(ah1));
        const uint al2 = cvt_tf32(a2f - __uint_as_float(ah2));
        const uint al3 = cvt_tf32(a3f - __uint_as_float(ah3));

#pragma unroll
        for (int nt = 0; nt < 4; nt++) {
            const float4 bf = __ldg(&Wf[(ks * 16 + warp * 4 + nt) * 32 + lane]);
            const uint bh0 = __float_as_uint(bf.x);
            const uint bh1 = __float_as_uint(bf.y);
            const uint bl0 = __float_as_uint(bf.z);
            const uint bl1 = __float_as_uint(bf.w);
            mma_tf32(d[nt][0], d[nt][1], d[nt][2], d[nt][3],
                     ah0, ah1, ah2, ah3, bh0, bh1);
            mma_tf32(d[nt][0], d[nt][1], d[nt][2], d[nt][3],
                     ah0, ah1, ah2, ah3, bl0, bl1);
            mma_tf32(d[nt][0], d[nt][1], d[nt][2], d[nt][3],
                     al0, al1, al2, al3, bh0, bh1);
        }
    }

    float psr0 = 0.f, psr8 = 0.f, pdr0 = 0.f, pdr8 = 0.f;
#pragma unroll
    for (int nt = 0; nt < 4; nt++) {
        const int col = warp * 32 + nt * 8 + 2 * tig;
        *(float2*)&g_h[(row0 + gid) * 128 + col]     = make_float2(d[nt][0], d[nt][1]);
        *(float2*)&g_h[(row0 + gid + 8) * 128 + col] = make_float2(d[nt][2], d[nt][3]);

        const float2 as = *(const float2*)&att_src[col];
        const float2 ad = *(const float2*)&att_dst[col];
        psr0 += d[nt][0] * as.x + d[nt][1] * as.y;
        psr8 += d[nt][2] * as.x + d[nt][3] * as.y;
        pdr0 += d[nt][0] * ad.x + d[nt][1] * ad.y;
        pdr8 += d[nt][2] * ad.x + d[nt][3] * ad.y;
    }
#pragma unroll
    for (int o = 1; o < 4; o <<= 1) {
        psr0 += __shfl_xor_sync(0xffffffffu, psr0, o);
        psr8 += __shfl_xor_sync(0xffffffffu, psr8, o);
        pdr0 += __shfl_xor_sync(0xffffffffu, pdr0, o);
        pdr8 += __shfl_xor_sync(0xffffffffu, pdr8, o);
    }
    if (tig == 0) {
        const int n0 = row0 + gid;
        const int n8 = row0 + gid + 8;
        int i4 = n0 * 4 + warp;
        g_A[i4] = psr0;  g_B[i4] = pdr0;
        g_EA[i4]  = __expf(psr0);        g_EB[i4]  = __expf(pdr0);
        g_EA5[i4] = __expf(0.2f * psr0); g_EB5[i4] = __expf(0.2f * pdr0);
        i4 = n8 * 4 + warp;
        g_A[i4] = psr8;  g_B[i4] = pdr8;
        g_EA[i4]  = __expf(psr8);        g_EB[i4]  = __expf(pdr8);
        g_EA5[i4] = __expf(0.2f * psr8); g_EB5[i4] = __expf(0.2f * pdr8);
    }
}

// ---------------------------------------------------------------------------
// K2: row aggregation via rank-sort + parallel prefix sums.
// Block = (r, head), grid = 192, 128 threads.
// ---------------------------------------------------------------------------
__global__ void __launch_bounds__(128)
k_row_agg()
{
    const int r   = blockIdx.x >> 2;
    const int hh  = blockIdx.x & 3;
    const int tid = threadIdx.x;

    __shared__ float Au[128], EAu[128], EA5u[128];
    __shared__ float Bu[128], EBu[128], EB5u[128];
    __shared__ float keys[128];
    __shared__ int   sidx[128];
    __shared__ __align__(16) float Vhi[128 * 36];
    __shared__ __align__(16) float Vlo[128 * 36];
    __shared__ float Es[128], E5s[128], Pe[128], Pe5[128];
    __shared__ float Qt[4][32];
    __shared__ float QtP[8];

    {
        const int idx = (r * 128 + tid) * 4 + hh;
        Au  [tid] = g_A  [idx];
        EAu [tid] = g_EA [idx];
        EA5u[tid] = g_EA5[idx];
        Bu  [tid] = g_B  [idx];
        EBu [tid] = g_EB [idx];
        EB5u[tid] = g_EB5[idx];
    }
    __syncthreads();

    // rank-by-counting sort (ties broken by index)
    {
        const float myk = Au[tid];
        int rank = 0;
#pragma unroll 8
        for (int j = 0; j < 128; j++) {
            const float kj = Au[j];
            rank += (kj < myk) || (kj == myk && j < tid);
        }
        keys[rank] = myk;
        sidx[rank] = tid;
    }
    __syncthreads();

    // build V tables in sorted order; thread = sorted position
    {
        const int j = sidx[tid];
        const float ea  = EAu[j];
        const float ea5 = EA5u[j];
        Es [tid] = ea;
        E5s[tid] = ea5;
        const float* hp = &g_h[(r * 128 + j) * 128 + hh * 32];
#pragma unroll
        for (int v = 0; v < 8; v++) {
            const float4 hv = *(const float4*)&hp[v * 4];
            *(float4*)&Vhi[tid * 36 + v * 4] =
                make_float4(ea * hv.x, ea * hv.y, ea * hv.z, ea * hv.w);
            *(float4*)&Vlo[tid * 36 + v * 4] =
                make_float4(ea5 * hv.x, ea5 * hv.y, ea5 * hv.z, ea5 * hv.w);
        }
    }
    __syncthreads();

    // parallel inclusive scans: thread = (quarter q, dim dt), 32 positions each
    const int q  = tid >> 5;
    const int dt = tid & 31;

    {   // hi table
        float t[32];
        float acc = 0.f;
#pragma unroll
        for (int i = 0; i < 32; i++) {
            acc += Vhi[(q * 32 + i) * 36 + dt];
            t[i] = acc;
        }
        Qt[q][dt] = acc;
        __syncthreads();
        float off = 0.f;
#pragma unroll
        for (int p = 0; p < 3; p++) if (p < q) off += Qt[p][dt];
#pragma unroll
        for (int i = 0; i < 32; i++)
            Vhi[(q * 32 + i) * 36 + dt] = t[i] + off;
    }
    __syncthreads();
    {   // lo table
        float t[32];
        float acc = 0.f;
#pragma unroll
        for (int i = 0; i < 32; i++) {
            acc += Vlo[(q * 32 + i) * 36 + dt];
            t[i] = acc;
        }
        Qt[q][dt] = acc;
        __syncthreads();
        float off = 0.f;
#pragma unroll
        for (int p = 0; p < 3; p++) if (p < q) off += Qt[p][dt];
#pragma unroll
        for (int i = 0; i < 32; i++)
            Vlo[(q * 32 + i) * 36 + dt] = t[i] + off;
    }
    // Pe / Pe5 scans: threads 0..3 (Pe quarters), 4..7 (Pe5 quarters)
    if (tid < 8) {
        const int qq = tid & 3;
        const bool is5 = tid >= 4;
        float acc = 0.f;
        for (int i = 0; i < 32; i++) {
            acc += is5 ? E5s[qq * 32 + i] : Es[qq * 32 + i];
            (is5 ? Pe5 : Pe)[qq * 32 + i] = acc;
        }
        QtP[tid] = acc;
    }
    __syncthreads();
    if (tid < 8) {
        const int qq = tid & 3;
        const bool is5 = tid >= 4;
        float off = 0.f;
        for (int p = (is5 ? 4 : 0); p < tid; p++) off += QtP[p];
        if (off != 0.f)
            for (int i = 0; i < 32; i++)
                (is5 ? Pe5 : Pe)[qq * 32 + i] += off;
    }
    __syncthreads();

    // per-dst combine: c = tid
    {
        const int c = tid;
        const float x = -Bu[c];
        int lo = 0, hi2 = 128;
        while (lo < hi2) {
            const int mid = (lo + hi2) >> 1;
            if (keys[mid] <= x) lo = mid + 1; else hi2 = mid;
        }
        const int R  = lo;
        const float f  = (R > 0) ? 1.f : 0.f;
        const int  Rm  = (R > 0) ? (R - 1) : 0;
        const float eb = EBu[c], eb5 = EB5u[c];

        g_srow[(r * 128 + c) * 4 + hh] =
            eb * (Pe[127] - f * Pe[Rm]) + eb5 * (f * Pe5[Rm]);

        float* op = &g_tmp[(r * 128 + c) * 128 + hh * 32];
#pragma unroll
        for (int v = 0; v < 8; v++) {
            const float4 thv = *(const float4*)&Vhi[127 * 36 + v * 4];
            const float4 phv = *(const float4*)&Vhi[Rm * 36 + v * 4];
            const float4 plv = *(const float4*)&Vlo[Rm * 36 + v * 4];
            float4 o;
            o.x = eb * (thv.x - f * phv.x) + eb5 * (f * plv.x);
            o.y = eb * (thv.y - f * phv.y) + eb5 * (f * plv.y);
            o.z = eb * (thv.z - f * phv.z) + eb5 * (f * plv.z);
            o.w = eb * (thv.w - f * phv.w) + eb5 * (f * plv.w);
            *(float4*)&op[v * 4] = o;
        }
    }
}

// ---------------------------------------------------------------------------
// K3: column aggregation via rank-sort + parallel prefix sums (48 srcs padded
// to 64) + denominator finalize + normalize + bias + ELU.
// Block = (c, head), grid = 512, 128 threads.
// ---------------------------------------------------------------------------
__global__ void __launch_bounds__(128)
k_col_agg(const float* __restrict__ bias, float* __restrict__ out)
{
    const int c   = blockIdx.x >> 2;
    const int hh  = blockIdx.x & 3;
    const int tid = threadIdx.x;

    __shared__ float Au[64], EAu[64], EA5u[64];
    __shared__ float Bu[48], EBu[48], EB5u[48], Srw[48];
    __shared__ float keys[64];
    __shared__ int   sidx[64];
    __shared__ __align__(16) float Vhi[64 * 36];
    __shared__ __align__(16) float Vlo[64 * 36];
    __shared__ float Es[64], E5s[64], Pe[64], Pe5[64];
    __shared__ float QtH[2][32], QtL[2][32];
    __shared__ float QtP[4];
    __shared__ float bsh[32];

    if (tid < 48) {
        const int idx = (tid * 128 + c) * 4 + hh;
        Au  [tid] = g_A   [idx];
        EAu [tid] = g_EA  [idx];
        EA5u[tid] = g_EA5 [idx];
        Bu  [tid] = g_B   [idx];
        EBu [tid] = g_EB  [idx];
        EB5u[tid] = g_EB5 [idx];
        Srw [tid] = g_srow[idx];
    } else if (tid < 64) {
        Au  [tid] = 1e30f;
        EAu [tid] = 0.f;
        EA5u[tid] = 0.f;
    } else if (tid < 96) {
        bsh[tid - 64] = bias[hh * 32 + (tid - 64)];
    }
    __syncthreads();

    // rank-by-counting over 64 keys (pads sort last)
    if (tid < 64) {
        const float myk = Au[tid];
        int rank = 0;
#pragma unroll 8
        for (int j = 0; j < 64; j++) {
            const float kj = Au[j];
            rank += (kj < myk) || (kj == myk && j < tid);
        }
        keys[rank] = myk;
        sidx[rank] = tid;
    }
    __syncthreads();

    // build V tables; thread = sorted position (0..63)
    if (tid < 64) {
        const int j = sidx[tid];
        const float ea  = EAu[j];
        const float ea5 = EA5u[j];
        Es [tid] = ea;
        E5s[tid] = ea5;
        if (j < 48) {
            const float* hp = &g_h[(j * 128 + c) * 128 + hh * 32];
#pragma unroll
            for (int v = 0; v < 8; v++) {
                const float4 hv = *(const float4*)&hp[v * 4];
                *(float4*)&Vhi[tid * 36 + v * 4] =
                    make_float4(ea * hv.x, ea * hv.y, ea * hv.z, ea * hv.w);
                *(float4*)&Vlo[tid * 36 + v * 4] =
                    make_float4(ea5 * hv.x, ea5 * hv.y, ea5 * hv.z, ea5 * hv.w);
            }
        } else {
            const float4 z = make_float4(0.f, 0.f, 0.f, 0.f);
#pragma unroll
            for (int v = 0; v < 8; v++) {
                *(float4*)&Vhi[tid * 36 + v * 4] = z;
                *(float4*)&Vlo[tid * 36 + v * 4] = z;
            }
        }
    }
    __syncthreads();

    // scans: threads 0..63 scan hi (2 halves x 32 dims), 64..127 scan lo
    {
        const bool isLo = tid >= 64;
        const int  lt   = isLo ? tid - 64 : tid;
        const int  q    = lt >> 5;           // half (0/1)
        const int  dt   = lt & 31;
        float* V = isLo ? Vlo : Vhi;
        float t[32];
        float acc = 0.f;
#pragma unroll
        for (int i = 0; i < 32; i++) {
            acc += V[(q * 32 + i) * 36 + dt];
            t[i] = acc;
        }
        (isLo ? QtL : QtH)[q][dt] = acc;
        __syncthreads();
        const float off = (q == 1) ? (isLo ? QtL : QtH)[0][dt] : 0.f;
#pragma unroll
        for (int i = 0; i < 32; i++)
            V[(q * 32 + i) * 36 + dt] = t[i] + off;
    }
    // Pe/Pe5: threads 0,1 = Pe halves; 2,3 = Pe5 halves
    if (tid < 4) {
        const int qq = tid & 1;
        const bool is5 = tid >= 2;
        float acc = 0.f;
        for (int i = 0; i < 32; i++) {
            acc += is5 ? E5s[qq * 32 + i] : Es[qq * 32 + i];
            (is5 ? Pe5 : Pe)[qq * 32 + i] = acc;
        }
        QtP[tid] = acc;
    }
    __syncthreads();
    if (tid < 4 && (tid & 1)) {
        const bool is5 = tid >= 2;
        const float off = QtP[is5 ? 2 : 0];
        for (int i = 0; i < 32; i++)
            (is5 ? Pe5 : Pe)[32 + i] += off;
    }
    __syncthreads();

    // combine: dst r = tid (0..47)
    if (tid < 48) {
        const int rr = tid;
        const float Bv = Bu[rr];
        const float x  = -Bv;
        int lo = 0, hi2 = 64;
        while (lo < hi2) {
            const int mid = (lo + hi2) >> 1;
            if (keys[mid] <= x) lo = mid + 1; else hi2 = mid;
        }
        const int R  = lo;
        const float f = (R > 0) ? 1.f : 0.f;
        const int  Rm = (R > 0) ? (R - 1) : 0;
        const float eb = EBu[rr], eb5 = EB5u[rr];

        const float xs2 = Au[rr] + Bv;
        const float wself = xs2 > 0.f ? EAu[rr] * eb : EA5u[rr] * eb5;

        const float scol = eb * (Pe[63] - f * Pe[Rm]) + eb5 * (f * Pe5[Rm]) - wself;
        const float rd = 1.f / (Srw[rr] + scol);

        const float* hs = &g_h  [(rr * 128 + c) * 128 + hh * 32];
        const float* tp = &g_tmp[(rr * 128 + c) * 128 + hh * 32];
        float*       op = &out  [(rr * 128 + c) * 128 + hh * 32];

#pragma unroll
        for (int v = 0; v < 8; v++) {
            const float4 hv  = *(const float4*)&hs[v * 4];
            const float4 tv  = *(const float4*)&tp[v * 4];
            const float4 thv = *(const float4*)&Vhi[63 * 36 + v * 4];
            const float4 phv = *(const float4*)&Vhi[Rm * 36 + v * 4];
            const float4 plv = *(const float4*)&Vlo[Rm * 36 + v * 4];
            float4 o;
            float vv;
            vv = (tv.x + eb * (thv.x - f * phv.x) + eb5 * (f * plv.x) - wself * hv.x) * rd + bsh[v*4+0];
            o.x = vv > 0.f ? vv : (__expf(vv) - 1.f);
            vv = (tv.y + eb * (thv.y - f * phv.y) + eb5 * (f * plv.y) - wself * hv.y) * rd + bsh[v*4+1];
            o.y = vv > 0.f ? vv : (__expf(vv) - 1.f);
            vv = (tv.z + eb * (thv.z - f * phv.z) + eb5 * (f * plv.z) - wself * hv.z) * rd + bsh[v*4+2];
            o.z = vv > 0.f ? vv : (__expf(vv) - 1.f);
            vv = (tv.w + eb * (thv.w - f * phv.w) + eb5 * (f * plv.w) - wself * hv.w) * rd + bsh[v*4+3];
            o.w = vv > 0.f ? vv : (__expf(vv) - 1.f);
            *(float4*)&op[v * 4] = o;
        }
    }
}

// ---------------------------------------------------------------------------
static void run_layer(const float* x, const float4* Wf, const float* asrc,
                      const float* adst, const float* bias, float* out)
{
    k_gemm_attn<<<NNODE / 16, 128>>>(x, Wf, asrc, adst);
    k_row_agg<<<T_TRIG * NHEADS, 128>>>();
    k_col_agg<<<S_SPAN * NHEADS, 128>>>(bias, out);
}

extern "C" void kernel_launch(void* const* d_in, const int* in_sizes, int n_in,
                              void* d_out, int out_size)
{
    const float* x0  = (const float*)d_in[0];
    const float* W1  = (const float*)d_in[1];
    const float* as1 = (const float*)d_in[2];
    const float* ad1 = (const float*)d_in[3];
    const float* b1  = (const float*)d_in[4];
    const float* W2  = (const float*)d_in[5];
    const float* as2 = (const float*)d_in[6];
    const float* ad2 = (const float*)d_in[7];
    const float* b2  = (const float*)d_in[8];

    float* x1 = nullptr;
    cudaGetSymbolAddress((void**)&x1, g_x1);
    float4* Wf = nullptr;
    cudaGetSymbolAddress((void**)&Wf, g_Wf);

    k_prep<<<64, 256>>>(W1, W2);
    run_layer(x0, Wf,        as1, ad1, b1, x1);
    run_layer(x1, Wf + 8192, as2, ad2, b2, (float*)d_out);
}